// round 8
// baseline (speedup 1.0000x reference)
#include <cuda_runtime.h>
#include <cuda_bf16.h>
#include <cstdint>

// B=2, S=512, D=256, N=16, DC=4, DI=512, CHUNK=32, rows=1024

// ---------------- scratch ----------------
__device__ __nv_bfloat16 g_xpb [1024*512];
__device__ float         g_sz  [1024*512];
__device__ float         g_xact[1024*512];
__device__ float         g_decay[1024*512];
__device__ __nv_bfloat16 g_Bmb [1024*16];
__device__ __nv_bfloat16 g_Cmb [1024*16];
__device__ float         g_invdeg[1024];
__device__ float         g_any [1024];
__device__ __nv_bfloat16 g_Pb  [1024*512];
__device__ __nv_bfloat16 g_Woutb[256*512];
__device__ __nv_bfloat16 g_adjb [2*512*512];
__device__ __nv_bfloat16 g_cwb  [4*512*512];   // [kc][n][k]

// ---------------- mma helpers ----------------
__device__ __forceinline__ uint32_t smem_u32(const void* p) {
    return (uint32_t)__cvta_generic_to_shared(p);
}
__device__ __forceinline__ void ldsm_x4(uint32_t* r, uint32_t a) {
    asm volatile("ldmatrix.sync.aligned.m8n8.x4.shared.b16 {%0,%1,%2,%3}, [%4];\n"
                 : "=r"(r[0]), "=r"(r[1]), "=r"(r[2]), "=r"(r[3]) : "r"(a));
}
__device__ __forceinline__ void ldsm_x4t(uint32_t* r, uint32_t a) {
    asm volatile("ldmatrix.sync.aligned.m8n8.x4.trans.shared.b16 {%0,%1,%2,%3}, [%4];\n"
                 : "=r"(r[0]), "=r"(r[1]), "=r"(r[2]), "=r"(r[3]) : "r"(a));
}
__device__ __forceinline__ void mma_bf16(float* c, const uint32_t* a, const uint32_t* b) {
    asm volatile(
        "mma.sync.aligned.m16n8k16.row.col.f32.bf16.bf16.f32 "
        "{%0,%1,%2,%3}, {%4,%5,%6,%7}, {%8,%9}, {%0,%1,%2,%3};\n"
        : "+f"(c[0]), "+f"(c[1]), "+f"(c[2]), "+f"(c[3])
        : "r"(a[0]), "r"(a[1]), "r"(a[2]), "r"(a[3]), "r"(b[0]), "r"(b[1]));
}
__device__ __forceinline__ uint4 pack8(float4 a, float4 b) {
    __nv_bfloat162 r0 = __floats2bfloat162_rn(a.x, a.y);
    __nv_bfloat162 r1 = __floats2bfloat162_rn(a.z, a.w);
    __nv_bfloat162 r2 = __floats2bfloat162_rn(b.x, b.y);
    __nv_bfloat162 r3 = __floats2bfloat162_rn(b.z, b.w);
    uint4 u;
    u.x = *(uint32_t*)&r0; u.y = *(uint32_t*)&r1;
    u.z = *(uint32_t*)&r2; u.w = *(uint32_t*)&r3;
    return u;
}
__device__ __forceinline__ float dot16_bf16(const __nv_bfloat16* h, const __nv_bfloat16* c) {
    uint4 h0 = *(const uint4*)h,       h1 = *(const uint4*)(h + 8);
    uint4 c0 = *(const uint4*)c,       c1 = *(const uint4*)(c + 8);
    const __nv_bfloat162* hp0 = (const __nv_bfloat162*)&h0;
    const __nv_bfloat162* hp1 = (const __nv_bfloat162*)&h1;
    const __nv_bfloat162* cp0 = (const __nv_bfloat162*)&c0;
    const __nv_bfloat162* cp1 = (const __nv_bfloat162*)&c1;
    float y = 0.f;
#pragma unroll
    for (int q = 0; q < 4; ++q) {
        float2 a = __bfloat1622float2(hp0[q]), bb = __bfloat1622float2(cp0[q]);
        y = fmaf(a.x, bb.x, y); y = fmaf(a.y, bb.y, y);
        float2 a1 = __bfloat1622float2(hp1[q]), b1 = __bfloat1622float2(cp1[q]);
        y = fmaf(a1.x, b1.x, y); y = fmaf(a1.y, b1.y, y);
    }
    return y;
}

// ---------------- GEMM ids ----------------
#define GEMM_IDS                                                                 \
    int tid = threadIdx.x, lane = tid & 31, wid = tid >> 5;                      \
    int wr = wid >> 1, wc = wid & 1;                                             \
    int srow = tid >> 1, shalf = tid & 1;                                        \
    int ar = wr * 32 + (lane & 15), ac = (lane >> 4) * 8;                        \
    int brw = wc * 32 + (lane & 7) + ((lane >> 4) * 8), bc = ((lane >> 3) & 1) * 8;

// ---------------- launch 1: LN + xz GEMM + conversions ----------------
__global__ void __launch_bounds__(128) gemm_xz(const float* __restrict__ x,
                                               const float* __restrict__ lnw,
                                               const float* __restrict__ lnb,
                                               const float* __restrict__ W_in,
                                               const float* __restrict__ conv_w,
                                               const float* __restrict__ adj,
                                               const float* __restrict__ W_out) {
    __shared__ __align__(16) __nv_bfloat16 Xs[64][264];
    __shared__ __align__(16) __nv_bfloat16 Ws[2][64][16];
    int m0 = blockIdx.y * 64, n0 = blockIdx.x * 64;
    GEMM_IDS
    (void)brw; (void)bc;

    {
        int r = tid >> 1, hf = tid & 1;
        const float4* xr = (const float4*)(x + (size_t)(m0 + r) * 256 + hf * 128);
        float s = 0.f, s2 = 0.f;
#pragma unroll 8
        for (int i = 0; i < 32; ++i) {
            float4 v = xr[i];
            s += v.x + v.y + v.z + v.w;
            s2 += v.x * v.x + v.y * v.y + v.z * v.z + v.w * v.w;
        }
        s  += __shfl_xor_sync(0xffffffffu, s, 1);
        s2 += __shfl_xor_sync(0xffffffffu, s2, 1);
        float mu = s * (1.f / 256.f);
        float var = s2 * (1.f / 256.f) - mu * mu;
        float rstd = rsqrtf(var + 1e-5f);
#pragma unroll 8
        for (int i = 0; i < 32; ++i) {
            float4 v = xr[i];
            int col = hf * 128 + i * 4;
            float4 w = *(const float4*)(lnw + col);
            float4 bb = *(const float4*)(lnb + col);
            Xs[r][col + 0] = __float2bfloat16((v.x - mu) * rstd * w.x + bb.x);
            Xs[r][col + 1] = __float2bfloat16((v.y - mu) * rstd * w.y + bb.y);
            Xs[r][col + 2] = __float2bfloat16((v.z - mu) * rstd * w.z + bb.z);
            Xs[r][col + 3] = __float2bfloat16((v.w - mu) * rstd * w.w + bb.w);
        }
    }

    float cfr[2][4][4] = {};
    auto ldW = [&](int k0) -> uint4 {
        const float* p = W_in + (size_t)(n0 + srow) * 256 + k0 + shalf * 8;
        return pack8(*(const float4*)p, *(const float4*)(p + 4));
    };
    uint4 pw = ldW(0);
    *(uint4*)&Ws[0][srow][shalf * 8] = pw;
    __syncthreads();
    int pb = 0;
    for (int k0 = 0; k0 < 256; k0 += 16, pb ^= 1) {
        if (k0 + 16 < 256) {
            pw = ldW(k0 + 16);
            *(uint4*)&Ws[pb ^ 1][srow][shalf * 8] = pw;
        }
        uint32_t afr[2][4], bfr[2][4];
        ldsm_x4(afr[0], smem_u32(&Xs[ar][k0 + ac]));
        ldsm_x4(afr[1], smem_u32(&Xs[ar + 16][k0 + ac]));
        {
            int brw2 = wc * 32 + (lane & 7) + ((lane >> 4) * 8), bc2 = ((lane >> 3) & 1) * 8;
            ldsm_x4(bfr[0], smem_u32(&Ws[pb][brw2][bc2]));
            ldsm_x4(bfr[1], smem_u32(&Ws[pb][brw2 + 16][bc2]));
        }
#pragma unroll
        for (int mt = 0; mt < 2; ++mt) {
            mma_bf16(cfr[mt][0], afr[mt], bfr[0] + 0);
            mma_bf16(cfr[mt][1], afr[mt], bfr[0] + 2);
            mma_bf16(cfr[mt][2], afr[mt], bfr[1] + 0);
            mma_bf16(cfr[mt][3], afr[mt], bfr[1] + 2);
        }
        __syncthreads();
    }
    int gr = lane >> 2, tc2 = (lane & 3) * 2;
#pragma unroll
    for (int mt = 0; mt < 2; ++mt)
#pragma unroll
        for (int nt = 0; nt < 4; ++nt)
#pragma unroll
            for (int e = 0; e < 4; ++e) {
                int m = m0 + wr * 32 + mt * 16 + gr + ((e >> 1) * 8);
                int n = n0 + wc * 32 + nt * 8 + tc2 + (e & 1);
                float v = cfr[mt][nt][e];
                if (n < 512) g_xpb[m * 512 + n] = __float2bfloat16(v);
                else         g_sz[m * 512 + (n - 512)] = v / (1.0f + __expf(-v));
            }

    int gtid = (blockIdx.y * gridDim.x + blockIdx.x) * 128 + tid;
    const int GT = 16 * 16 * 128;
    for (int i = gtid; i < 4 * 512 * 512; i += GT) {
        int kc = i >> 18, nn = (i >> 9) & 511, kk = i & 511;
        g_cwb[i] = __float2bfloat16(conv_w[nn * 2048 + kk * 4 + kc]);
    }
    for (int i = gtid; i < 2 * 512 * 512; i += GT)
        g_adjb[i] = __float2bfloat16(adj[i]);
    for (int i = gtid; i < 256 * 512; i += GT)
        g_Woutb[i] = __float2bfloat16(W_out[i]);
}

// ---------------- launch 2: conv GEMM (32-col stages, reg prefetch depth 2) ----------------
__global__ void __launch_bounds__(128) gemm_conv(const float* __restrict__ conv_b) {
    __shared__ __align__(16) __nv_bfloat16 As[2][64][32];
    __shared__ __align__(16) __nv_bfloat16 Ws[2][64][32];
    int m0 = blockIdx.y * 64, n0 = blockIdx.x * 64;
    GEMM_IDS
    float cfr[2][4][4] = {};
    // stage it: kc = it>>4, 32 cols at (it&15)*32
    auto ldA = [&](int it, uint4* v) {
        int kc = it >> 4, k0 = (it & 15) << 5;
        int tsrc = ((m0 + srow) & 511) - 3 + kc;
        v[0] = make_uint4(0u, 0u, 0u, 0u); v[1] = v[0];
        if (tsrc >= 0) {
            const __nv_bfloat16* p = &g_xpb[(long long)(m0 + srow - 3 + kc) * 512 + k0 + shalf * 8];
            v[0] = *(const uint4*)p;
            v[1] = *(const uint4*)(p + 16);
        }
    };
    auto ldW = [&](int it, uint4* v) {
        int kc = it >> 4, k0 = (it & 15) << 5;
        const __nv_bfloat16* p = &g_cwb[kc * 262144 + (n0 + srow) * 512 + k0 + shalf * 8];
        v[0] = *(const uint4*)p;
        v[1] = *(const uint4*)(p + 16);
    };
    uint4 ra[2], rw[2];
    ldA(0, ra); ldW(0, rw);
    *(uint4*)&As[0][srow][shalf * 8]      = ra[0];
    *(uint4*)&As[0][srow][16 + shalf * 8] = ra[1];
    *(uint4*)&Ws[0][srow][shalf * 8]      = rw[0];
    *(uint4*)&Ws[0][srow][16 + shalf * 8] = rw[1];
    ldA(1, ra); ldW(1, rw);
    for (int it = 0; it < 64; ++it) {
        __syncthreads();
        int pb = it & 1;
        if (it + 1 < 64) {
            int nb = pb ^ 1;
            *(uint4*)&As[nb][srow][shalf * 8]      = ra[0];
            *(uint4*)&As[nb][srow][16 + shalf * 8] = ra[1];
            *(uint4*)&Ws[nb][srow][shalf * 8]      = rw[0];
            *(uint4*)&Ws[nb][srow][16 + shalf * 8] = rw[1];
            if (it + 2 < 64) { ldA(it + 2, ra); ldW(it + 2, rw); }
        }
#pragma unroll
        for (int ks = 0; ks < 2; ++ks) {
            uint32_t afr[2][4], bfr[2][4];
            ldsm_x4(afr[0], smem_u32(&As[pb][ar][ks * 16 + ac]));
            ldsm_x4(afr[1], smem_u32(&As[pb][ar + 16][ks * 16 + ac]));
            ldsm_x4(bfr[0], smem_u32(&Ws[pb][brw][ks * 16 + bc]));
            ldsm_x4(bfr[1], smem_u32(&Ws[pb][brw + 16][ks * 16 + bc]));
#pragma unroll
            for (int mt = 0; mt < 2; ++mt) {
                mma_bf16(cfr[mt][0], afr[mt], bfr[0] + 0);
                mma_bf16(cfr[mt][1], afr[mt], bfr[0] + 2);
                mma_bf16(cfr[mt][2], afr[mt], bfr[1] + 0);
                mma_bf16(cfr[mt][3], afr[mt], bfr[1] + 2);
            }
        }
    }
    int gr = lane >> 2, tc2 = (lane & 3) * 2;
#pragma unroll
    for (int mt = 0; mt < 2; ++mt)
#pragma unroll
        for (int nt = 0; nt < 4; ++nt)
#pragma unroll
            for (int e = 0; e < 4; ++e) {
                int m = m0 + wr * 32 + mt * 16 + gr + ((e >> 1) * 8);
                int n = n0 + wc * 32 + nt * 8 + tc2 + (e & 1);
                float v = cfr[mt][nt][e] + conv_b[n];
                g_xact[m * 512 + n] = v / (1.0f + __expf(-v));
            }
}

// ---------------- launch 3: ssm + deg ----------------
__global__ void __launch_bounds__(128) ssm_deg(const float* __restrict__ W_xp,
                                               const float* __restrict__ W_dt,
                                               const float* __restrict__ b_dt,
                                               const float* __restrict__ adj) {
    __shared__ float xs[512];
    __shared__ float ssm_sh[33];
    __shared__ float rs[4];
    __shared__ int   ra[4];
    int row = blockIdx.x, tid = threadIdx.x, lane = tid & 31, wid = tid >> 5;
    int t = row & 511;

    for (int i = tid; i < 512; i += 128) xs[i] = g_xact[row * 512 + i];

    {
        const float* a = adj + (size_t)row * 512;
        float s = 0.f; int any = 0;
        for (int i = tid; i < t; i += 128) { float v = a[i]; s += v; any |= (v > 0.f); }
        for (int k = 16; k > 0; k >>= 1) {
            s += __shfl_xor_sync(0xffffffffu, s, k);
            any |= __shfl_xor_sync(0xffffffffu, any, k);
        }
        if (lane == 0) { rs[wid] = s; ra[wid] = any; }
    }
    __syncthreads();
    if (tid == 0) {
        float s = rs[0] + rs[1] + rs[2] + rs[3];
        int any = ra[0] | ra[1] | ra[2] | ra[3];
        g_invdeg[row] = 1.0f / fmaxf(s, 1.0f);
        g_any[row] = any ? 1.f : 0.f;
    }
    for (int o = wid; o < 33; o += 4) {
        float p = 0.f;
        for (int i = lane; i < 512; i += 32) p += xs[i] * W_xp[o * 512 + i];
        for (int k = 16; k > 0; k >>= 1) p += __shfl_xor_sync(0xffffffffu, p, k);
        if (lane == 0) ssm_sh[o] = p;
    }
    __syncthreads();
    if (tid < 16) {
        g_Bmb[row * 16 + tid] = __float2bfloat16(ssm_sh[1 + tid]);
        g_Cmb[row * 16 + tid] = __float2bfloat16(ssm_sh[17 + tid]);
    }
    float s0 = ssm_sh[0];
    for (int d = tid; d < 512; d += 128) {
        float v = s0 * W_dt[d] + b_dt[d];
        g_decay[row * 512 + d] = 1.0f / (1.0f + expf(v));  // exp(-softplus(v))
    }
}

// ---------------- launch 4: scan (branch-free serial step) ----------------
__global__ void __launch_bounds__(128, 7) scan_kernel(const float* __restrict__ Wr,
                                                      const float* __restrict__ br) {
    __shared__ __align__(16) __nv_bfloat16 hist[512][16];       // 16384
    __shared__ __align__(16) float Gsh[32][16];                 // 2048
    __shared__ __align__(16) unsigned char ubuf[4][2048];       // 8192
    __shared__ __align__(16) __nv_bfloat16 adjTf[32][32];       // 2048, [j][t] = adj[c0+t][c0+j]
    __shared__ __align__(16) float xB_s[32][16];                // 2048
    __shared__ __align__(16) float4 scal_s[32];                 // 512: (dec, cond, ivd[j+1], 0)
    __shared__ __align__(16) float gtmp[16];
    __shared__ float ivd0_s;

#define ADJS(w_) ((__nv_bfloat16(*)[32])ubuf[w_])
#define GPf(w_)  ((float(*)[16])ubuf[w_])

    int tid = threadIdx.x, lane = tid & 31, wid = tid >> 5;
    int seq = blockIdx.x, b = seq >> 9, d = seq & 511;
    const long long badj = (long long)b * 512 * 512;

    float Wr_r[16], br_r = 0.f, Greg[16], hreg = 0.f;
    int n = lane & 15;
    if (wid == 0) {
#pragma unroll
        for (int m = 0; m < 16; ++m) Wr_r[m] = Wr[n * 16 + m];
        br_r = br[n];
    }

    for (int c = 0; c < 16; ++c) {
        int c0 = c << 5;

        // ================= PHASE A =================
        if (wid == 1) {
            if (c == 0) {
                for (int e = lane; e < 512; e += 32) Gsh[e >> 4][e & 15] = 0.f;
            } else {
                float cfr2[2][2][4] = {};
                int sb = (c - 1) << 5;
                uint32_t afr[4], bfr[4];
#pragma unroll
                for (int kt = 0; kt < 2; ++kt) {
                    ldsm_x4t(bfr, smem_u32(&hist[sb + kt * 16 + (lane & 15)][(lane >> 4) * 8]));
#pragma unroll
                    for (int mt = 0; mt < 2; ++mt) {
                        ldsm_x4(afr, smem_u32(&ADJS(3)[mt * 16 + (lane & 15)][kt * 16 + (lane >> 4) * 8]));
                        mma_bf16(cfr2[mt][0], afr, bfr + 0);
                        mma_bf16(cfr2[mt][1], afr, bfr + 2);
                    }
                }
                int gr = lane >> 2, tc2 = (lane & 3) * 2;
#pragma unroll
                for (int mt = 0; mt < 2; ++mt)
#pragma unroll
                    for (int nt = 0; nt < 2; ++nt)
#pragma unroll
                        for (int e = 0; e < 4; ++e) {
                            int r = mt * 16 + gr + (e >> 1) * 8;
                            int col = nt * 8 + tc2 + (e & 1);
                            Gsh[r][col] = GPf(0)[r][col] + GPf(1)[r][col] + GPf(2)[r][col]
                                          + cfr2[mt][nt][e];
                        }
            }
        } else if (wid == 2) {
            int j = lane;
            int row = b * 512 + c0 + j;
            float xa = g_xact[(size_t)row * 512 + d];
            float dec = g_decay[(size_t)row * 512 + d];
            int t = c0 + j;
            float cond = (t > 0 && (g_any[t] > 0.f || g_any[512 + t] > 0.f)) ? 1.f : 0.f;
            float ivdn = (j < 31) ? g_invdeg[row + 1] : 0.f;
            scal_s[j] = make_float4(dec, cond, ivdn, 0.f);
            if (j == 0) ivd0_s = g_invdeg[row];
            uint4 bm = *(const uint4*)&g_Bmb[row * 16];
            __nv_bfloat162* bp = (__nv_bfloat162*)&bm;
#pragma unroll
            for (int q = 0; q < 8; ++q) {
                float2 f = __bfloat1622float2(bp[q]);
                xB_s[j][2 * q]     = xa * f.x;
                xB_s[j][2 * q + 1] = xa * f.y;
            }
        } else if (wid == 3) {
            __nv_bfloat16 rowv[32];
            const __nv_bfloat16* src = &g_adjb[badj + (long long)(c0 + lane) * 512 + c0];
            *(uint4*)&rowv[0]  = *(const uint4*)(src + 0);
            *(uint4*)&rowv[8]  = *(const uint4*)(src + 8);
            *(uint4*)&rowv[16] = *(const uint4*)(src + 16);
            *(uint4*)&rowv[24] = *(const uint4*)(src + 24);
#pragma unroll
            for (int s = 0; s < 32; ++s) adjTf[s][lane] = rowv[s];
        }
        __syncthreads();

        // ================= PHASE B =================
        if (wid == 0) {
            bool hi = lane >= 16;
            int rbase = hi ? 16 : 0;
#pragma unroll
            for (int q = 0; q < 16; ++q) Greg[q] = Gsh[rbase + q][n];
            if (!hi) gtmp[n] = Greg[0] * ivd0_s;   // predicated store
            __syncwarp();
#pragma unroll
            for (int j = 0; j < 32; ++j) {
                // broadcast g of row j
                float4 g0 = *(const float4*)&gtmp[0];
                float4 g1 = *(const float4*)&gtmp[4];
                float4 g2 = *(const float4*)&gtmp[8];
                float4 g3 = *(const float4*)&gtmp[12];
                // scatter coefficients (own 16 rows at column j)
                uint4 au0 = *(const uint4*)&adjTf[j][rbase];
                uint4 au1 = *(const uint4*)&adjTf[j][rbase + 8];
                float av[16];
                {
                    const __nv_bfloat162* ap0 = (const __nv_bfloat162*)&au0;
                    const __nv_bfloat162* ap1 = (const __nv_bfloat162*)&au1;
#pragma unroll
                    for (int k = 0; k < 4; ++k) {
                        float2 f0 = __bfloat1622float2(ap0[k]);
                        av[2 * k] = f0.x; av[2 * k + 1] = f0.y;
                        float2 f1 = __bfloat1622float2(ap1[k]);
                        av[8 + 2 * k] = f1.x; av[8 + 2 * k + 1] = f1.y;
                    }
                }
                float4 sc = scal_s[j];
                float xb = xB_s[j][n];
                // matvec (4 parallel chains)
                float p0 = fmaf(Wr_r[0], g0.x, br_r);
                float p1 = Wr_r[1] * g0.y;
                float p2 = Wr_r[2] * g0.z;
                float p3 = Wr_r[3] * g0.w;
                p0 = fmaf(Wr_r[4], g1.x, p0);
                p1 = fmaf(Wr_r[5], g1.y, p1);
                p2 = fmaf(Wr_r[6], g1.z, p2);
                p3 = fmaf(Wr_r[7], g1.w, p3);
                p0 = fmaf(Wr_r[8], g2.x, p0);
                p1 = fmaf(Wr_r[9], g2.y, p1);
                p2 = fmaf(Wr_r[10], g2.z, p2);
                p3 = fmaf(Wr_r[11], g2.w, p3);
                p0 = fmaf(Wr_r[12], g3.x, p0);
                p1 = fmaf(Wr_r[13], g3.y, p1);
                p2 = fmaf(Wr_r[14], g3.z, p2);
                p3 = fmaf(Wr_r[15], g3.w, p3);
                float accb = (p0 + p1) + (p2 + p3);
                float bo = 0.1f * __fdividef(accb, 1.0f + __expf(-accb));
                float h = fmaf(hreg, sc.x, xb);
                h = fmaf(sc.y, bo, h);
                hreg = h;
                if (lane < 16) hist[c0 + j][n] = __float2bfloat16(h);  // both halves same h
                if (j < 31) {
                    // row j+1 update first, publish, then the rest (dead rows harmless)
                    const int qn = (j + 1) & 15;
                    Greg[qn] = fmaf(av[qn], h, Greg[qn]);
                    bool owner = ((j + 1) >= 16) == hi;
                    if (owner) gtmp[n] = Greg[qn] * sc.z;  // predicated store
                    __syncwarp();
#pragma unroll
                    for (int q = 0; q < 16; ++q)
                        if (q != qn) Greg[q] = fmaf(av[q], h, Greg[q]);
                }
            }
        } else {
            int w = wid - 1;
            float cfr[2][2][4] = {};
            if (c < 15) {
                int r1 = (c + 1) << 5;
                for (int st = w; st < c; st += 3) {
#pragma unroll
                    for (int k = 0; k < 4; ++k) {
                        int e = lane + 32 * k, tt = e >> 2, q = e & 3;
                        *(uint4*)&ADJS(w)[tt][q * 8] =
                            *(const uint4*)&g_adjb[badj + (long long)(r1 + tt) * 512 + st * 32 + q * 8];
                    }
                    __syncwarp();
                    int sb = st << 5;
                    uint32_t afr[4], bfr[4];
#pragma unroll
                    for (int kt = 0; kt < 2; ++kt) {
                        ldsm_x4t(bfr, smem_u32(&hist[sb + kt * 16 + (lane & 15)][(lane >> 4) * 8]));
#pragma unroll
                        for (int mt = 0; mt < 2; ++mt) {
                            ldsm_x4(afr, smem_u32(&ADJS(w)[mt * 16 + (lane & 15)][kt * 16 + (lane >> 4) * 8]));
                            mma_bf16(cfr[mt][0], afr, bfr + 0);
                            mma_bf16(cfr[mt][1], afr, bfr + 2);
                        }
                    }
                    __syncwarp();
                }
            }
            {
                int gr = lane >> 2, tc2 = (lane & 3) * 2;
#pragma unroll
                for (int mt = 0; mt < 2; ++mt)
#pragma unroll
                    for (int nt = 0; nt < 2; ++nt)
#pragma unroll
                        for (int e = 0; e < 4; ++e) {
                            int r = mt * 16 + gr + (e >> 1) * 8;
                            int col = nt * 8 + tc2 + (e & 1);
                            GPf(w)[r][col] = cfr[mt][nt][e];
                        }
            }
            if (wid == 1 && c < 15) {
                int r1 = (c + 1) << 5;
#pragma unroll
                for (int k = 0; k < 4; ++k) {
                    int e = lane + 32 * k, tt = e >> 2, q = e & 3;
                    *(uint4*)&ADJS(3)[tt][q * 8] =
                        *(const uint4*)&g_adjb[badj + (long long)(r1 + tt) * 512 + c0 + q * 8];
                }
            }
            if (wid == 3 && c > 0) {
                int cp0 = (c - 1) << 5;
                int rowg = b * 512 + cp0 + lane;
                float y = dot16_bf16(&hist[cp0 + lane][0], &g_Cmb[rowg * 16]);
                g_Pb[(long long)rowg * 512 + d] =
                    __float2bfloat16(y * g_sz[(long long)rowg * 512 + d]);
            }
        }
        __syncthreads();
    }

    if (tid < 32) {
        int cp0 = 15 << 5;
        int rowg = b * 512 + cp0 + tid;
        float y = dot16_bf16(&hist[cp0 + tid][0], &g_Cmb[rowg * 16]);
        g_Pb[(long long)rowg * 512 + d] =
            __float2bfloat16(y * g_sz[(long long)rowg * 512 + d]);
    }
#undef ADJS
#undef GPf
}

// ---------------- launch 5: out GEMM + residual ----------------
__global__ void __launch_bounds__(128) gemm_out(const float* __restrict__ x,
                                                float* __restrict__ out) {
    __shared__ __align__(16) __nv_bfloat16 As[2][64][16];
    __shared__ __align__(16) __nv_bfloat16 Ws[2][64][16];
    int m0 = blockIdx.y * 64, n0 = blockIdx.x * 64;
    GEMM_IDS
    float cfr[2][4][4] = {};
    *(uint4*)&As[0][srow][shalf * 8] = *(const uint4*)&g_Pb[(m0 + srow) * 512 + shalf * 8];
    *(uint4*)&Ws[0][srow][shalf * 8] = *(const uint4*)&g_Woutb[(n0 + srow) * 512 + shalf * 8];
    __syncthreads();
    int pb = 0;
    for (int k0 = 0; k0 < 512; k0 += 16, pb ^= 1) {
        if (k0 + 16 < 512) {
            *(uint4*)&As[pb ^ 1][srow][shalf * 8] =
                *(const uint4*)&g_Pb[(m0 + srow) * 512 + k0 + 16 + shalf * 8];
            *(uint4*)&Ws[pb ^ 1][srow][shalf * 8] =
                *(const uint4*)&g_Woutb[(n0 + srow) * 512 + k0 + 16 + shalf * 8];
        }
        uint32_t afr[2][4], bfr[2][4];
        ldsm_x4(afr[0], smem_u32(&As[pb][ar][ac]));
        ldsm_x4(afr[1], smem_u32(&As[pb][ar + 16][ac]));
        ldsm_x4(bfr[0], smem_u32(&Ws[pb][brw][bc]));
        ldsm_x4(bfr[1], smem_u32(&Ws[pb][brw + 16][bc]));
#pragma unroll
        for (int mt = 0; mt < 2; ++mt) {
            mma_bf16(cfr[mt][0], afr[mt], bfr[0] + 0);
            mma_bf16(cfr[mt][1], afr[mt], bfr[0] + 2);
            mma_bf16(cfr[mt][2], afr[mt], bfr[1] + 0);
            mma_bf16(cfr[mt][3], afr[mt], bfr[1] + 2);
        }
        __syncthreads();
    }
    int gr = lane >> 2, tc2 = (lane & 3) * 2;
#pragma unroll
    for (int mt = 0; mt < 2; ++mt)
#pragma unroll
        for (int nt = 0; nt < 4; ++nt)
#pragma unroll
            for (int e = 0; e < 4; ++e) {
                int m = m0 + wr * 32 + mt * 16 + gr + ((e >> 1) * 8);
                int n = n0 + wc * 32 + nt * 8 + tc2 + (e & 1);
                out[m * 256 + n] = cfr[mt][nt][e] + x[m * 256 + n];
            }
}

// ---------------- launch ----------------
extern "C" void kernel_launch(void* const* d_in, const int* in_sizes, int n_in,
                              void* d_out, int out_size) {
    const float* x      = (const float*)d_in[0];
    const float* adj    = (const float*)d_in[1];
    const float* ln_w   = (const float*)d_in[2];
    const float* ln_b   = (const float*)d_in[3];
    const float* W_in   = (const float*)d_in[4];
    const float* conv_w = (const float*)d_in[5];
    const float* conv_b = (const float*)d_in[6];
    const float* W_xp   = (const float*)d_in[7];
    const float* W_dt   = (const float*)d_in[8];
    const float* b_dt   = (const float*)d_in[9];
    const float* Wr     = (const float*)d_in[10];
    const float* br     = (const float*)d_in[11];
    const float* W_out  = (const float*)d_in[12];
    float* out = (float*)d_out;

    gemm_xz<<<dim3(16, 16), 128>>>(x, ln_w, ln_b, W_in, conv_w, adj, W_out);
    gemm_conv<<<dim3(8, 16), 128>>>(conv_b);
    ssm_deg<<<1024, 128>>>(W_xp, W_dt, b_dt, adj);
    scan_kernel<<<1024, 128>>>(Wr, br);
    gemm_out<<<dim3(4, 16), 128>>>(x, out);
}

// round 9
// speedup vs baseline: 1.0919x; 1.0919x over previous
#include <cuda_runtime.h>
#include <cuda_bf16.h>
#include <cstdint>

// B=2, S=512, D=256, N=16, DC=4, DI=512, CHUNK=32, rows=1024

// ---------------- scratch ----------------
__device__ __nv_bfloat16 g_xpb [1024*512];
__device__ float         g_sz  [1024*512];
__device__ float         g_xact[1024*512];
__device__ float         g_decay[1024*512];
__device__ __nv_bfloat16 g_Bmb [1024*16];
__device__ __nv_bfloat16 g_Cmb [1024*16];
__device__ float         g_invdeg[1024];
__device__ float         g_any [1024];
__device__ __nv_bfloat16 g_Pb  [1024*512];
__device__ __nv_bfloat16 g_Woutb[256*512];
__device__ __nv_bfloat16 g_adjb [2*512*512];
__device__ __nv_bfloat16 g_cwb  [4*512*512];   // [kc][n][k]

// ---------------- mma helpers ----------------
__device__ __forceinline__ uint32_t smem_u32(const void* p) {
    return (uint32_t)__cvta_generic_to_shared(p);
}
__device__ __forceinline__ void ldsm_x4(uint32_t* r, uint32_t a) {
    asm volatile("ldmatrix.sync.aligned.m8n8.x4.shared.b16 {%0,%1,%2,%3}, [%4];\n"
                 : "=r"(r[0]), "=r"(r[1]), "=r"(r[2]), "=r"(r[3]) : "r"(a));
}
__device__ __forceinline__ void ldsm_x4t(uint32_t* r, uint32_t a) {
    asm volatile("ldmatrix.sync.aligned.m8n8.x4.trans.shared.b16 {%0,%1,%2,%3}, [%4];\n"
                 : "=r"(r[0]), "=r"(r[1]), "=r"(r[2]), "=r"(r[3]) : "r"(a));
}
__device__ __forceinline__ void mma_bf16(float* c, const uint32_t* a, const uint32_t* b) {
    asm volatile(
        "mma.sync.aligned.m16n8k16.row.col.f32.bf16.bf16.f32 "
        "{%0,%1,%2,%3}, {%4,%5,%6,%7}, {%8,%9}, {%0,%1,%2,%3};\n"
        : "+f"(c[0]), "+f"(c[1]), "+f"(c[2]), "+f"(c[3])
        : "r"(a[0]), "r"(a[1]), "r"(a[2]), "r"(a[3]), "r"(b[0]), "r"(b[1]));
}
__device__ __forceinline__ uint4 pack8(float4 a, float4 b) {
    __nv_bfloat162 r0 = __floats2bfloat162_rn(a.x, a.y);
    __nv_bfloat162 r1 = __floats2bfloat162_rn(a.z, a.w);
    __nv_bfloat162 r2 = __floats2bfloat162_rn(b.x, b.y);
    __nv_bfloat162 r3 = __floats2bfloat162_rn(b.z, b.w);
    uint4 u;
    u.x = *(uint32_t*)&r0; u.y = *(uint32_t*)&r1;
    u.z = *(uint32_t*)&r2; u.w = *(uint32_t*)&r3;
    return u;
}
__device__ __forceinline__ float dot16_bf16(const __nv_bfloat16* h, const __nv_bfloat16* c) {
    uint4 h0 = *(const uint4*)h,       h1 = *(const uint4*)(h + 8);
    uint4 c0 = *(const uint4*)c,       c1 = *(const uint4*)(c + 8);
    const __nv_bfloat162* hp0 = (const __nv_bfloat162*)&h0;
    const __nv_bfloat162* hp1 = (const __nv_bfloat162*)&h1;
    const __nv_bfloat162* cp0 = (const __nv_bfloat162*)&c0;
    const __nv_bfloat162* cp1 = (const __nv_bfloat162*)&c1;
    float y = 0.f;
#pragma unroll
    for (int q = 0; q < 4; ++q) {
        float2 a = __bfloat1622float2(hp0[q]), bb = __bfloat1622float2(cp0[q]);
        y = fmaf(a.x, bb.x, y); y = fmaf(a.y, bb.y, y);
        float2 a1 = __bfloat1622float2(hp1[q]), b1 = __bfloat1622float2(cp1[q]);
        y = fmaf(a1.x, b1.x, y); y = fmaf(a1.y, b1.y, y);
    }
    return y;
}
// 0.1 * silu(x) via hardware tanh:  x*(0.05 + 0.05*tanh(0.5x))
__device__ __forceinline__ float boost_silu(float x) {
    float th;
    asm("tanh.approx.f32 %0, %1;" : "=f"(th) : "f"(x * 0.5f));
    return x * fmaf(th, 0.05f, 0.05f);
}

// ---------------- GEMM ids ----------------
#define GEMM_IDS                                                                 \
    int tid = threadIdx.x, lane = tid & 31, wid = tid >> 5;                      \
    int wr = wid >> 1, wc = wid & 1;                                             \
    int srow = tid >> 1, shalf = tid & 1;                                        \
    int ar = wr * 32 + (lane & 15), ac = (lane >> 4) * 8;                        \
    int brw = wc * 32 + (lane & 7) + ((lane >> 4) * 8), bc = ((lane >> 3) & 1) * 8;

// ---------------- launch 1: LN + xz GEMM + conversions ----------------
__global__ void __launch_bounds__(128) gemm_xz(const float* __restrict__ x,
                                               const float* __restrict__ lnw,
                                               const float* __restrict__ lnb,
                                               const float* __restrict__ W_in,
                                               const float* __restrict__ conv_w,
                                               const float* __restrict__ adj,
                                               const float* __restrict__ W_out) {
    __shared__ __align__(16) __nv_bfloat16 Xs[64][264];
    __shared__ __align__(16) __nv_bfloat16 Ws[2][64][16];
    int m0 = blockIdx.y * 64, n0 = blockIdx.x * 64;
    GEMM_IDS
    (void)brw; (void)bc;

    {
        int r = tid >> 1, hf = tid & 1;
        const float4* xr = (const float4*)(x + (size_t)(m0 + r) * 256 + hf * 128);
        float s = 0.f, s2 = 0.f;
#pragma unroll 8
        for (int i = 0; i < 32; ++i) {
            float4 v = xr[i];
            s += v.x + v.y + v.z + v.w;
            s2 += v.x * v.x + v.y * v.y + v.z * v.z + v.w * v.w;
        }
        s  += __shfl_xor_sync(0xffffffffu, s, 1);
        s2 += __shfl_xor_sync(0xffffffffu, s2, 1);
        float mu = s * (1.f / 256.f);
        float var = s2 * (1.f / 256.f) - mu * mu;
        float rstd = rsqrtf(var + 1e-5f);
#pragma unroll 8
        for (int i = 0; i < 32; ++i) {
            float4 v = xr[i];
            int col = hf * 128 + i * 4;
            float4 w = *(const float4*)(lnw + col);
            float4 bb = *(const float4*)(lnb + col);
            Xs[r][col + 0] = __float2bfloat16((v.x - mu) * rstd * w.x + bb.x);
            Xs[r][col + 1] = __float2bfloat16((v.y - mu) * rstd * w.y + bb.y);
            Xs[r][col + 2] = __float2bfloat16((v.z - mu) * rstd * w.z + bb.z);
            Xs[r][col + 3] = __float2bfloat16((v.w - mu) * rstd * w.w + bb.w);
        }
    }

    float cfr[2][4][4] = {};
    auto ldW = [&](int k0) -> uint4 {
        const float* p = W_in + (size_t)(n0 + srow) * 256 + k0 + shalf * 8;
        return pack8(*(const float4*)p, *(const float4*)(p + 4));
    };
    uint4 pw = ldW(0);
    *(uint4*)&Ws[0][srow][shalf * 8] = pw;
    __syncthreads();
    int pb = 0;
    for (int k0 = 0; k0 < 256; k0 += 16, pb ^= 1) {
        if (k0 + 16 < 256) {
            pw = ldW(k0 + 16);
            *(uint4*)&Ws[pb ^ 1][srow][shalf * 8] = pw;
        }
        uint32_t afr[2][4], bfr[2][4];
        ldsm_x4(afr[0], smem_u32(&Xs[ar][k0 + ac]));
        ldsm_x4(afr[1], smem_u32(&Xs[ar + 16][k0 + ac]));
        {
            int brw2 = wc * 32 + (lane & 7) + ((lane >> 4) * 8), bc2 = ((lane >> 3) & 1) * 8;
            ldsm_x4(bfr[0], smem_u32(&Ws[pb][brw2][bc2]));
            ldsm_x4(bfr[1], smem_u32(&Ws[pb][brw2 + 16][bc2]));
        }
#pragma unroll
        for (int mt = 0; mt < 2; ++mt) {
            mma_bf16(cfr[mt][0], afr[mt], bfr[0] + 0);
            mma_bf16(cfr[mt][1], afr[mt], bfr[0] + 2);
            mma_bf16(cfr[mt][2], afr[mt], bfr[1] + 0);
            mma_bf16(cfr[mt][3], afr[mt], bfr[1] + 2);
        }
        __syncthreads();
    }
    int gr = lane >> 2, tc2 = (lane & 3) * 2;
#pragma unroll
    for (int mt = 0; mt < 2; ++mt)
#pragma unroll
        for (int nt = 0; nt < 4; ++nt)
#pragma unroll
            for (int e = 0; e < 4; ++e) {
                int m = m0 + wr * 32 + mt * 16 + gr + ((e >> 1) * 8);
                int n = n0 + wc * 32 + nt * 8 + tc2 + (e & 1);
                float v = cfr[mt][nt][e];
                if (n < 512) g_xpb[m * 512 + n] = __float2bfloat16(v);
                else         g_sz[m * 512 + (n - 512)] = v / (1.0f + __expf(-v));
            }

    int gtid = (blockIdx.y * gridDim.x + blockIdx.x) * 128 + tid;
    const int GT = 16 * 16 * 128;
    for (int i = gtid; i < 4 * 512 * 512; i += GT) {
        int kc = i >> 18, nn = (i >> 9) & 511, kk = i & 511;
        g_cwb[i] = __float2bfloat16(conv_w[nn * 2048 + kk * 4 + kc]);
    }
    for (int i = gtid; i < 2 * 512 * 512; i += GT)
        g_adjb[i] = __float2bfloat16(adj[i]);
    for (int i = gtid; i < 256 * 512; i += GT)
        g_Woutb[i] = __float2bfloat16(W_out[i]);
}

// ---------------- launch 2: conv GEMM (32-col stages, reg prefetch depth 2) ----------------
__global__ void __launch_bounds__(128) gemm_conv(const float* __restrict__ conv_b) {
    __shared__ __align__(16) __nv_bfloat16 As[2][64][32];
    __shared__ __align__(16) __nv_bfloat16 Ws[2][64][32];
    int m0 = blockIdx.y * 64, n0 = blockIdx.x * 64;
    GEMM_IDS
    float cfr[2][4][4] = {};
    auto ldA = [&](int it, uint4* v) {
        int kc = it >> 4, k0 = (it & 15) << 5;
        int tsrc = ((m0 + srow) & 511) - 3 + kc;
        v[0] = make_uint4(0u, 0u, 0u, 0u); v[1] = v[0];
        if (tsrc >= 0) {
            const __nv_bfloat16* p = &g_xpb[(long long)(m0 + srow - 3 + kc) * 512 + k0 + shalf * 8];
            v[0] = *(const uint4*)p;
            v[1] = *(const uint4*)(p + 16);
        }
    };
    auto ldW = [&](int it, uint4* v) {
        int kc = it >> 4, k0 = (it & 15) << 5;
        const __nv_bfloat16* p = &g_cwb[kc * 262144 + (n0 + srow) * 512 + k0 + shalf * 8];
        v[0] = *(const uint4*)p;
        v[1] = *(const uint4*)(p + 16);
    };
    uint4 ra[2], rw[2];
    ldA(0, ra); ldW(0, rw);
    *(uint4*)&As[0][srow][shalf * 8]      = ra[0];
    *(uint4*)&As[0][srow][16 + shalf * 8] = ra[1];
    *(uint4*)&Ws[0][srow][shalf * 8]      = rw[0];
    *(uint4*)&Ws[0][srow][16 + shalf * 8] = rw[1];
    ldA(1, ra); ldW(1, rw);
    for (int it = 0; it < 64; ++it) {
        __syncthreads();
        int pb = it & 1;
        if (it + 1 < 64) {
            int nb = pb ^ 1;
            *(uint4*)&As[nb][srow][shalf * 8]      = ra[0];
            *(uint4*)&As[nb][srow][16 + shalf * 8] = ra[1];
            *(uint4*)&Ws[nb][srow][shalf * 8]      = rw[0];
            *(uint4*)&Ws[nb][srow][16 + shalf * 8] = rw[1];
            if (it + 2 < 64) { ldA(it + 2, ra); ldW(it + 2, rw); }
        }
#pragma unroll
        for (int ks = 0; ks < 2; ++ks) {
            uint32_t afr[2][4], bfr[2][4];
            ldsm_x4(afr[0], smem_u32(&As[pb][ar][ks * 16 + ac]));
            ldsm_x4(afr[1], smem_u32(&As[pb][ar + 16][ks * 16 + ac]));
            ldsm_x4(bfr[0], smem_u32(&Ws[pb][brw][ks * 16 + bc]));
            ldsm_x4(bfr[1], smem_u32(&Ws[pb][brw + 16][ks * 16 + bc]));
#pragma unroll
            for (int mt = 0; mt < 2; ++mt) {
                mma_bf16(cfr[mt][0], afr[mt], bfr[0] + 0);
                mma_bf16(cfr[mt][1], afr[mt], bfr[0] + 2);
                mma_bf16(cfr[mt][2], afr[mt], bfr[1] + 0);
                mma_bf16(cfr[mt][3], afr[mt], bfr[1] + 2);
            }
        }
    }
    int gr = lane >> 2, tc2 = (lane & 3) * 2;
#pragma unroll
    for (int mt = 0; mt < 2; ++mt)
#pragma unroll
        for (int nt = 0; nt < 4; ++nt)
#pragma unroll
            for (int e = 0; e < 4; ++e) {
                int m = m0 + wr * 32 + mt * 16 + gr + ((e >> 1) * 8);
                int n = n0 + wc * 32 + nt * 8 + tc2 + (e & 1);
                float v = cfr[mt][nt][e] + conv_b[n];
                g_xact[m * 512 + n] = v / (1.0f + __expf(-v));
            }
}

// ---------------- launch 3: ssm + deg ----------------
__global__ void __launch_bounds__(128) ssm_deg(const float* __restrict__ W_xp,
                                               const float* __restrict__ W_dt,
                                               const float* __restrict__ b_dt,
                                               const float* __restrict__ adj) {
    __shared__ float xs[512];
    __shared__ float ssm_sh[33];
    __shared__ float rs[4];
    __shared__ int   ra[4];
    int row = blockIdx.x, tid = threadIdx.x, lane = tid & 31, wid = tid >> 5;
    int t = row & 511;

    for (int i = tid; i < 512; i += 128) xs[i] = g_xact[row * 512 + i];

    {
        const float* a = adj + (size_t)row * 512;
        float s = 0.f; int any = 0;
        for (int i = tid; i < t; i += 128) { float v = a[i]; s += v; any |= (v > 0.f); }
        for (int k = 16; k > 0; k >>= 1) {
            s += __shfl_xor_sync(0xffffffffu, s, k);
            any |= __shfl_xor_sync(0xffffffffu, any, k);
        }
        if (lane == 0) { rs[wid] = s; ra[wid] = any; }
    }
    __syncthreads();
    if (tid == 0) {
        float s = rs[0] + rs[1] + rs[2] + rs[3];
        int any = ra[0] | ra[1] | ra[2] | ra[3];
        g_invdeg[row] = 1.0f / fmaxf(s, 1.0f);
        g_any[row] = any ? 1.f : 0.f;
    }
    for (int o = wid; o < 33; o += 4) {
        float p = 0.f;
        for (int i = lane; i < 512; i += 32) p += xs[i] * W_xp[o * 512 + i];
        for (int k = 16; k > 0; k >>= 1) p += __shfl_xor_sync(0xffffffffu, p, k);
        if (lane == 0) ssm_sh[o] = p;
    }
    __syncthreads();
    if (tid < 16) {
        g_Bmb[row * 16 + tid] = __float2bfloat16(ssm_sh[1 + tid]);
        g_Cmb[row * 16 + tid] = __float2bfloat16(ssm_sh[17 + tid]);
    }
    float s0 = ssm_sh[0];
    for (int d = tid; d < 512; d += 128) {
        float v = s0 * W_dt[d] + b_dt[d];
        g_decay[row * 512 + d] = 1.0f / (1.0f + expf(v));  // exp(-softplus(v))
    }
}

// ---------------- launch 4: scan (R6 structure + fast tanh silu) ----------------
__global__ void __launch_bounds__(128, 7) scan_kernel(const float* __restrict__ Wr,
                                                      const float* __restrict__ br) {
    __shared__ __align__(16) __nv_bfloat16 hist[512][16];       // 16384
    __shared__ __align__(16) float Gsh[32][16];                 // 2048
    __shared__ __align__(16) unsigned char ubuf[4][2048];       // 8192
    __shared__ __align__(16) __nv_bfloat16 adjTf[32][32];       // 2048, [j][t] = adj[c0+t][c0+j]
    __shared__ __align__(16) float xB_s[32][16];                // 2048
    __shared__ __align__(16) float4 scal_s[32];                 // 512: (dec, cond, ivd[j+1], 0)
    __shared__ __align__(16) float gtmp[16];
    __shared__ float ivd0_s;

#define ADJS(w_) ((__nv_bfloat16(*)[32])ubuf[w_])
#define GPf(w_)  ((float(*)[16])ubuf[w_])

    int tid = threadIdx.x, lane = tid & 31, wid = tid >> 5;
    int seq = blockIdx.x, b = seq >> 9, d = seq & 511;
    const long long badj = (long long)b * 512 * 512;

    float Wr_r[16], br_r = 0.f, Greg[16], hreg = 0.f;
    int n = lane & 15;
    if (wid == 0) {
#pragma unroll
        for (int m = 0; m < 16; ++m) Wr_r[m] = Wr[n * 16 + m];
        br_r = br[n];
    }

    for (int c = 0; c < 16; ++c) {
        int c0 = c << 5;

        // ================= PHASE A =================
        if (wid == 1) {
            if (c == 0) {
                for (int e = lane; e < 512; e += 32) Gsh[e >> 4][e & 15] = 0.f;
            } else {
                float cfr2[2][2][4] = {};
                int sb = (c - 1) << 5;
                uint32_t afr[4], bfr[4];
#pragma unroll
                for (int kt = 0; kt < 2; ++kt) {
                    ldsm_x4t(bfr, smem_u32(&hist[sb + kt * 16 + (lane & 15)][(lane >> 4) * 8]));
#pragma unroll
                    for (int mt = 0; mt < 2; ++mt) {
                        ldsm_x4(afr, smem_u32(&ADJS(3)[mt * 16 + (lane & 15)][kt * 16 + (lane >> 4) * 8]));
                        mma_bf16(cfr2[mt][0], afr, bfr + 0);
                        mma_bf16(cfr2[mt][1], afr, bfr + 2);
                    }
                }
                int gr = lane >> 2, tc2 = (lane & 3) * 2;
#pragma unroll
                for (int mt = 0; mt < 2; ++mt)
#pragma unroll
                    for (int nt = 0; nt < 2; ++nt)
#pragma unroll
                        for (int e = 0; e < 4; ++e) {
                            int r = mt * 16 + gr + (e >> 1) * 8;
                            int col = nt * 8 + tc2 + (e & 1);
                            Gsh[r][col] = GPf(0)[r][col] + GPf(1)[r][col] + GPf(2)[r][col]
                                          + cfr2[mt][nt][e];
                        }
            }
        } else if (wid == 2) {
            int j = lane;
            int row = b * 512 + c0 + j;
            float xa = g_xact[(size_t)row * 512 + d];
            float dec = g_decay[(size_t)row * 512 + d];
            int t = c0 + j;
            float cond = (t > 0 && (g_any[t] > 0.f || g_any[512 + t] > 0.f)) ? 1.f : 0.f;
            float ivdn = (j < 31) ? g_invdeg[row + 1] : 0.f;
            scal_s[j] = make_float4(dec, cond, ivdn, 0.f);
            if (j == 0) ivd0_s = g_invdeg[row];
            uint4 bm = *(const uint4*)&g_Bmb[row * 16];
            __nv_bfloat162* bp = (__nv_bfloat162*)&bm;
#pragma unroll
            for (int q = 0; q < 8; ++q) {
                float2 f = __bfloat1622float2(bp[q]);
                xB_s[j][2 * q]     = xa * f.x;
                xB_s[j][2 * q + 1] = xa * f.y;
            }
        } else if (wid == 3) {
            __nv_bfloat16 rowv[32];
            const __nv_bfloat16* src = &g_adjb[badj + (long long)(c0 + lane) * 512 + c0];
            *(uint4*)&rowv[0]  = *(const uint4*)(src + 0);
            *(uint4*)&rowv[8]  = *(const uint4*)(src + 8);
            *(uint4*)&rowv[16] = *(const uint4*)(src + 16);
            *(uint4*)&rowv[24] = *(const uint4*)(src + 24);
#pragma unroll
            for (int s = 0; s < 32; ++s) adjTf[s][lane] = rowv[s];
        }
        __syncthreads();

        // ================= PHASE B =================
        if (wid == 0) {
            bool hi = lane >= 16;
            int rbase = hi ? 16 : 0;
#pragma unroll
            for (int q = 0; q < 16; ++q) Greg[q] = Gsh[rbase + q][n];
            if (!hi) gtmp[n] = Greg[0] * ivd0_s;
            __syncwarp();
#pragma unroll
            for (int j = 0; j < 32; ++j) {
                float4 g0 = *(const float4*)&gtmp[0];
                float4 g1 = *(const float4*)&gtmp[4];
                float4 g2 = *(const float4*)&gtmp[8];
                float4 g3 = *(const float4*)&gtmp[12];
                uint4 au0 = *(const uint4*)&adjTf[j][rbase];
                uint4 au1 = *(const uint4*)&adjTf[j][rbase + 8];
                float av[16];
                {
                    const __nv_bfloat162* ap0 = (const __nv_bfloat162*)&au0;
                    const __nv_bfloat162* ap1 = (const __nv_bfloat162*)&au1;
#pragma unroll
                    for (int k = 0; k < 4; ++k) {
                        float2 f0 = __bfloat1622float2(ap0[k]);
                        av[2 * k] = f0.x; av[2 * k + 1] = f0.y;
                        float2 f1 = __bfloat1622float2(ap1[k]);
                        av[8 + 2 * k] = f1.x; av[8 + 2 * k + 1] = f1.y;
                    }
                }
                float4 sc = scal_s[j];
                float xb = xB_s[j][n];
                // matvec: 8 parallel chains, depth 2
                float p0 = fmaf(Wr_r[0], g0.x, br_r);
                float p1 = Wr_r[1] * g0.y;
                float p2 = Wr_r[2] * g0.z;
                float p3 = Wr_r[3] * g0.w;
                float p4 = Wr_r[4] * g1.x;
                float p5 = Wr_r[5] * g1.y;
                float p6 = Wr_r[6] * g1.z;
                float p7 = Wr_r[7] * g1.w;
                p0 = fmaf(Wr_r[8],  g2.x, p0);
                p1 = fmaf(Wr_r[9],  g2.y, p1);
                p2 = fmaf(Wr_r[10], g2.z, p2);
                p3 = fmaf(Wr_r[11], g2.w, p3);
                p4 = fmaf(Wr_r[12], g3.x, p4);
                p5 = fmaf(Wr_r[13], g3.y, p5);
                p6 = fmaf(Wr_r[14], g3.z, p6);
                p7 = fmaf(Wr_r[15], g3.w, p7);
                float accb = ((p0 + p1) + (p2 + p3)) + ((p4 + p5) + (p6 + p7));
                float bo = boost_silu(accb);
                float h = fmaf(hreg, sc.x, xb);
                h = fmaf(sc.y, bo, h);
                hreg = h;
                if (!hi) hist[c0 + j][n] = __float2bfloat16(h);
                if (j + 1 < 32) {
                    bool owner = (j + 1 >= 16);
                    if (hi == owner) {
                        int qn = (j + 1) & 15;
                        Greg[qn] = fmaf(av[qn], h, Greg[qn]);
                        gtmp[n] = Greg[qn] * sc.z;
                    }
                }
                __syncwarp();
                if (!hi) {
#pragma unroll
                    for (int q = 0; q < 16; ++q)
                        if (q > j && q != j + 1) Greg[q] = fmaf(av[q], h, Greg[q]);
                } else {
#pragma unroll
                    for (int q = 0; q < 16; ++q)
                        if (16 + q > j && 16 + q != j + 1) Greg[q] = fmaf(av[q], h, Greg[q]);
                }
            }
        } else {
            int w = wid - 1;
            float cfr[2][2][4] = {};
            if (c < 15) {
                int r1 = (c + 1) << 5;
                for (int st = w; st < c; st += 3) {
#pragma unroll
                    for (int k = 0; k < 4; ++k) {
                        int e = lane + 32 * k, tt = e >> 2, q = e & 3;
                        *(uint4*)&ADJS(w)[tt][q * 8] =
                            *(const uint4*)&g_adjb[badj + (long long)(r1 + tt) * 512 + st * 32 + q * 8];
                    }
                    __syncwarp();
                    int sb = st << 5;
                    uint32_t afr[4], bfr[4];
#pragma unroll
                    for (int kt = 0; kt < 2; ++kt) {
                        ldsm_x4t(bfr, smem_u32(&hist[sb + kt * 16 + (lane & 15)][(lane >> 4) * 8]));
#pragma unroll
                        for (int mt = 0; mt < 2; ++mt) {
                            ldsm_x4(afr, smem_u32(&ADJS(w)[mt * 16 + (lane & 15)][kt * 16 + (lane >> 4) * 8]));
                            mma_bf16(cfr[mt][0], afr, bfr + 0);
                            mma_bf16(cfr[mt][1], afr, bfr + 2);
                        }
                    }
                    __syncwarp();
                }
            }
            {
                int gr = lane >> 2, tc2 = (lane & 3) * 2;
#pragma unroll
                for (int mt = 0; mt < 2; ++mt)
#pragma unroll
                    for (int nt = 0; nt < 2; ++nt)
#pragma unroll
                        for (int e = 0; e < 4; ++e) {
                            int r = mt * 16 + gr + (e >> 1) * 8;
                            int col = nt * 8 + tc2 + (e & 1);
                            GPf(w)[r][col] = cfr[mt][nt][e];
                        }
            }
            if (wid == 1 && c < 15) {
                int r1 = (c + 1) << 5;
#pragma unroll
                for (int k = 0; k < 4; ++k) {
                    int e = lane + 32 * k, tt = e >> 2, q = e & 3;
                    *(uint4*)&ADJS(3)[tt][q * 8] =
                        *(const uint4*)&g_adjb[badj + (long long)(r1 + tt) * 512 + c0 + q * 8];
                }
            }
            if (wid == 3 && c > 0) {
                int cp0 = (c - 1) << 5;
                int rowg = b * 512 + cp0 + lane;
                float y = dot16_bf16(&hist[cp0 + lane][0], &g_Cmb[rowg * 16]);
                g_Pb[(long long)rowg * 512 + d] =
                    __float2bfloat16(y * g_sz[(long long)rowg * 512 + d]);
            }
        }
        __syncthreads();
    }

    if (tid < 32) {
        int cp0 = 15 << 5;
        int rowg = b * 512 + cp0 + tid;
        float y = dot16_bf16(&hist[cp0 + tid][0], &g_Cmb[rowg * 16]);
        g_Pb[(long long)rowg * 512 + d] =
            __float2bfloat16(y * g_sz[(long long)rowg * 512 + d]);
    }
#undef ADJS
#undef GPf
}

// ---------------- launch 5: out GEMM + residual ----------------
__global__ void __launch_bounds__(128) gemm_out(const float* __restrict__ x,
                                                float* __restrict__ out) {
    __shared__ __align__(16) __nv_bfloat16 As[2][64][16];
    __shared__ __align__(16) __nv_bfloat16 Ws[2][64][16];
    int m0 = blockIdx.y * 64, n0 = blockIdx.x * 64;
    GEMM_IDS
    float cfr[2][4][4] = {};
    *(uint4*)&As[0][srow][shalf * 8] = *(const uint4*)&g_Pb[(m0 + srow) * 512 + shalf * 8];
    *(uint4*)&Ws[0][srow][shalf * 8] = *(const uint4*)&g_Woutb[(n0 + srow) * 512 + shalf * 8];
    __syncthreads();
    int pb = 0;
    for (int k0 = 0; k0 < 512; k0 += 16, pb ^= 1) {
        if (k0 + 16 < 512) {
            *(uint4*)&As[pb ^ 1][srow][shalf * 8] =
                *(const uint4*)&g_Pb[(m0 + srow) * 512 + k0 + 16 + shalf * 8];
            *(uint4*)&Ws[pb ^ 1][srow][shalf * 8] =
                *(const uint4*)&g_Woutb[(n0 + srow) * 512 + k0 + 16 + shalf * 8];
        }
        uint32_t afr[2][4], bfr[2][4];
        ldsm_x4(afr[0], smem_u32(&As[pb][ar][ac]));
        ldsm_x4(afr[1], smem_u32(&As[pb][ar + 16][ac]));
        ldsm_x4(bfr[0], smem_u32(&Ws[pb][brw][bc]));
        ldsm_x4(bfr[1], smem_u32(&Ws[pb][brw + 16][bc]));
#pragma unroll
        for (int mt = 0; mt < 2; ++mt) {
            mma_bf16(cfr[mt][0], afr[mt], bfr[0] + 0);
            mma_bf16(cfr[mt][1], afr[mt], bfr[0] + 2);
            mma_bf16(cfr[mt][2], afr[mt], bfr[1] + 0);
            mma_bf16(cfr[mt][3], afr[mt], bfr[1] + 2);
        }
        __syncthreads();
    }
    int gr = lane >> 2, tc2 = (lane & 3) * 2;
#pragma unroll
    for (int mt = 0; mt < 2; ++mt)
#pragma unroll
        for (int nt = 0; nt < 4; ++nt)
#pragma unroll
            for (int e = 0; e < 4; ++e) {
                int m = m0 + wr * 32 + mt * 16 + gr + ((e >> 1) * 8);
                int n = n0 + wc * 32 + nt * 8 + tc2 + (e & 1);
                out[m * 256 + n] = cfr[mt][nt][e] + x[m * 256 + n];
            }
}

// ---------------- launch ----------------
extern "C" void kernel_launch(void* const* d_in, const int* in_sizes, int n_in,
                              void* d_out, int out_size) {
    const float* x      = (const float*)d_in[0];
    const float* adj    = (const float*)d_in[1];
    const float* ln_w   = (const float*)d_in[2];
    const float* ln_b   = (const float*)d_in[3];
    const float* W_in   = (const float*)d_in[4];
    const float* conv_w = (const float*)d_in[5];
    const float* conv_b = (const float*)d_in[6];
    const float* W_xp   = (const float*)d_in[7];
    const float* W_dt   = (const float*)d_in[8];
    const float* b_dt   = (const float*)d_in[9];
    const float* Wr     = (const float*)d_in[10];
    const float* br     = (const float*)d_in[11];
    const float* W_out  = (const float*)d_in[12];
    float* out = (float*)d_out;

    gemm_xz<<<dim3(16, 16), 128>>>(x, ln_w, ln_b, W_in, conv_w, adj, W_out);
    gemm_conv<<<dim3(8, 16), 128>>>(conv_b);
    ssm_deg<<<1024, 128>>>(W_xp, W_dt, b_dt, adj);
    scan_kernel<<<1024, 128>>>(Wr, br);
    gemm_out<<<dim3(4, 16), 128>>>(x, out);
}